// round 5
// baseline (speedup 1.0000x reference)
#include <cuda_runtime.h>
#include <cuda_bf16.h>

// T=50, H=W=8, NH=16, B=8, TP=TF=8, HIDDEN=512, RPE_COEF=16
#define NROW   22275          // 99*15*15
#define NROWP  22288          // padded to mult of 16 for aligned STG.128
#define NHEAD  16
#define HIDDEN 512
#define HPAD   20             // smem row stride (floats)

// Scratch: g_rpt[nh][row] = 16*sigmoid( (relu(rct@W1+b1)@W2)[row][nh] )
__device__ float g_rpt[NHEAD * NROWP];

// ---- packed f32x2 helpers (Blackwell) --------------------------------------
__device__ __forceinline__ unsigned long long pk64(float lo, float hi) {
    unsigned long long r;
    asm("mov.b64 %0, {%1, %2};" : "=l"(r) : "f"(lo), "f"(hi));
    return r;
}
__device__ __forceinline__ void upk64(unsigned long long v, float& lo, float& hi) {
    asm("mov.b64 {%0, %1}, %2;" : "=f"(lo), "=f"(hi) : "l"(v));
}
__device__ __forceinline__ unsigned long long fma2(unsigned long long a,
                                                   unsigned long long b,
                                                   unsigned long long c) {
    unsigned long long d;
    asm("fma.rn.f32x2 %0, %1, %2, %3;" : "=l"(d) : "l"(a), "l"(b), "l"(c));
    return d;
}

// ---------------------------------------------------------------------------
// Kernel 1: cpb MLP, fused 16*sigmoid, transposed store.
// 16 rows/block, 256 threads (8 warps).
//  Phase 1: warp w computes hidden for rows 2w, 2w+1 (fp32, padded smem).
//  Phase 2: warp w owns h-slice [w*64, w*64+64); thread = (nh, 8 rows);
//           4 x fma.rn.f32x2 per h; 8-way bank-padded smem reduction.
// ---------------------------------------------------------------------------
__global__ void __launch_bounds__(256) mlp_kernel(
    const float* __restrict__ rct,   // [NROW, 3]
    const float* __restrict__ W1,    // [3, 512]
    const float* __restrict__ b1,    // [512]
    const float* __restrict__ W2)    // [512, 16]
{
    __shared__ float sH[HIDDEN * HPAD];     // 40 KB: sH[h*HPAD + r], r in [0,16)
    const int t    = threadIdx.x;
    const int w    = t >> 5;                // warp 0..7
    const int lane = t & 31;
    const int row0 = blockIdx.x * 16;

    // ---- Phase 1: hidden layer. Warp w -> rows (2w, 2w+1). ----
    {
        const int r0 = row0 + 2 * w;
        const int r1 = r0 + 1;
        float c00 = 0.f, c01 = 0.f, c02 = 0.f;
        float c10 = 0.f, c11 = 0.f, c12 = 0.f;
        if (r0 < NROW) { c00 = __ldg(rct + r0 * 3 + 0);
                         c01 = __ldg(rct + r0 * 3 + 1);
                         c02 = __ldg(rct + r0 * 3 + 2); }
        if (r1 < NROW) { c10 = __ldg(rct + r1 * 3 + 0);
                         c11 = __ldg(rct + r1 * 3 + 1);
                         c12 = __ldg(rct + r1 * 3 + 2); }
        #pragma unroll 4
        for (int i = 0; i < 16; i++) {
            const int h  = i * 32 + lane;
            const float w0 = __ldg(W1 + h);
            const float w1 = __ldg(W1 + HIDDEN + h);
            const float w2 = __ldg(W1 + 2 * HIDDEN + h);
            const float bb = __ldg(b1 + h);
            float2 hv;
            hv.x = fmaxf(fmaf(c02, w2, fmaf(c01, w1, fmaf(c00, w0, bb))), 0.f);
            hv.y = fmaxf(fmaf(c12, w2, fmaf(c11, w1, fmaf(c10, w0, bb))), 0.f);
            *reinterpret_cast<float2*>(&sH[h * HPAD + 2 * w]) = hv;   // 8B aligned
        }
    }
    __syncthreads();

    // ---- Phase 2: layer 2, h-slice per warp ----
    const int oct = lane >> 4;              // rows oct*8 .. oct*8+7
    const int nh  = lane & 15;
    unsigned long long acc0 = 0ull, acc1 = 0ull, acc2 = 0ull, acc3 = 0ull;
    const int h0 = w * 64;
    const float* __restrict__ w2p = W2 + nh;
    #pragma unroll 4
    for (int i = 0; i < 64; i++) {
        const int h = h0 + i;
        const float wv = __ldg(w2p + h * NHEAD);         // L1-resident (32 KB)
        const unsigned long long ww = pk64(wv, wv);
        const float4 ha = *reinterpret_cast<const float4*>(&sH[h * HPAD + oct * 8]);
        const float4 hb = *reinterpret_cast<const float4*>(&sH[h * HPAD + oct * 8 + 4]);
        acc0 = fma2(pk64(ha.x, ha.y), ww, acc0);
        acc1 = fma2(pk64(ha.z, ha.w), ww, acc1);
        acc2 = fma2(pk64(hb.x, hb.y), ww, acc2);
        acc3 = fma2(pk64(hb.z, hb.w), ww, acc3);
    }
    __syncthreads();                         // done reading sH: reuse for reduction

    float a[8];
    upk64(acc0, a[0], a[1]); upk64(acc1, a[2], a[3]);
    upk64(acc2, a[4], a[5]); upk64(acc3, a[6], a[7]);

    // 8-way reduction: warps 1..7 store (stride-9 padding -> conflict-free),
    // warp 0 accumulates, activates, writes.
    float* sRed = sH;
    if (w > 0) {
        const int base = ((w - 1) * 32 + lane) * 9;
        #pragma unroll
        for (int j = 0; j < 8; j++) sRed[base + j] = a[j];
    }
    __syncthreads();
    if (w == 0) {
        #pragma unroll
        for (int q = 0; q < 7; q++) {
            const int base = (q * 32 + lane) * 9;
            #pragma unroll
            for (int j = 0; j < 8; j++) a[j] += sRed[base + j];
        }
        #pragma unroll
        for (int j = 0; j < 8; j++) a[j] = 16.f / (1.f + __expf(-a[j]));
        float* dst = g_rpt + nh * NROWP + row0 + oct * 8;
        *reinterpret_cast<float4*>(dst)     = make_float4(a[0], a[1], a[2], a[3]);
        *reinterpret_cast<float4*>(dst + 4) = make_float4(a[4], a[5], a[6], a[7]);
    }
}

// ---------------------------------------------------------------------------
// Kernel 2: gather. One block per (b, nh, tf, tp) 64x64 tile.
// Build the 240 DISTINCT output float4s (vtab[wf][dh+7][par], par = wp0/4)
// directly from the L2-resident table, then the hot loop is a single
// conflict-free LDS.128 + streaming STG.128 per output float4.
//   idx = (t_f + t_p)*225 + (hf-hp+7)*15 + (wf-wp+7)
// ---------------------------------------------------------------------------
__global__ void __launch_bounds__(256) gather_kernel(
    const int* __restrict__ ptc,     // [B, 8] (non-positive; time = -ptc)
    const int* __restrict__ ftc,     // [B, 8]
    float4* __restrict__ out)        // [B, 16, 512, 512] / 4
{
    __shared__ float4 vtab[240];     // [wf][dh+7][par] : wf*30 + dh7*2 + par
    const int tid = threadIdx.x;
    const int blk = blockIdx.x;
    const int tp = blk & 7;
    const int tf = (blk >> 3) & 7;
    const int nh = (blk >> 6) & 15;
    const int b  = blk >> 10;

    const int t_f =  __ldg(ftc + b * 8 + tf);
    const int t_p = -__ldg(ptc + b * 8 + tp);
    const float* __restrict__ src = g_rpt + nh * NROWP + (t_f + t_p) * 225;

    if (tid < 240) {
        const int wf  = tid / 30;
        const int rem = tid - wf * 30;
        const int dh7 = rem >> 1;
        const int par = rem & 1;                       // wp0 = par*4
        const int si  = dh7 * 15 + wf - par * 4 + 7;   // in [3, 224]
        vtab[tid] = make_float4(__ldg(src + si),     __ldg(src + si - 1),
                                __ldg(src + si - 2), __ldg(src + si - 3));
    }
    __syncthreads();

    // output tile base (float4 units): ((b*16+nh)*512 + tf*64)*512 + tp*64
    float4* __restrict__ out4 =
        out + ((((b * NHEAD + nh) * 512 + tf * 64) * 512 + tp * 64) >> 2);

    #pragma unroll
    for (int k = 0; k < 4; k++) {
        const int j   = tid + k * 256;           // 0..1023 = 64 rows x 16 float4
        const int c4  = j & 15;
        const int fhw = j >> 4;                  // output row 0..63
        const int wf  = fhw & 7;
        const int hf  = (fhw >> 3) & 7;
        const int hp  = c4 >> 1;
        const int par = c4 & 1;
        const float4 v = vtab[wf * 30 + (hf - hp + 7) * 2 + par];
        __stcs(out4 + fhw * 128 + c4, v);
    }
}

// ---------------------------------------------------------------------------
// Launch. Input order: ptc, ftc, W1, b1, W2, rct, rpi_table (unused).
// ---------------------------------------------------------------------------
extern "C" void kernel_launch(void* const* d_in, const int* in_sizes, int n_in,
                              void* d_out, int out_size)
{
    const int*   ptc = (const int*)  d_in[0];
    const int*   ftc = (const int*)  d_in[1];
    const float* W1  = (const float*)d_in[2];
    const float* b1  = (const float*)d_in[3];
    const float* W2  = (const float*)d_in[4];
    const float* rct = (const float*)d_in[5];

    mlp_kernel<<<NROWP / 16, 256>>>(rct, W1, b1, W2);

    // 8192 blocks: one per (b, nh, tf, tp) 64x64 tile
    gather_kernel<<<8 * NHEAD * 8 * 8, 256>>>(ptc, ftc, (float4*)d_out);
}